// round 14
// baseline (speedup 1.0000x reference)
#include <cuda_runtime.h>
#include <cstdint>

#define BQ     2048
#define IND    512
#define OUTD   512
#define NEXP   64

#define MT     128            // M: W rows per item
#define NTILE  32             // N: samples per item
#define BK     32             // k per stage
#define NSTAGE (IND / BK)     // 16
#define NT     128            // 4 warps
#define GRID_GEMM 512         // worst case: (64 + 2048/32) chunks * 4 mtiles
#define MAXITEMS 640

#define APITCH 36             // floats per A smem row (144B: ldmatrix conflict-free)
#define BPITCH 36
#define A_F    (MT * APITCH)       // 4608 floats
#define B_F    (NTILE * BPITCH)    // 1152 floats
#define SMEM_DYN ((2 * (A_F + B_F)) * 4)   // 46080 B

__device__ int g_count[NEXP];
__device__ int g_list[NEXP * BQ];
__device__ int g_items[MAXITEMS];
__device__ int g_nitems;

// ---------------- prep ----------------
__global__ void prep_kernel(const int* __restrict__ ids) {
    __shared__ int sc[NEXP];
    int t = threadIdx.x;
    if (t < NEXP) sc[t] = 0;
    __syncthreads();
    for (int i = t; i < BQ; i += blockDim.x) {
        int e = ids[i];
        if ((unsigned)e < NEXP) {
            int p = atomicAdd(&sc[e], 1);
            g_list[e * BQ + p] = i;
        }
    }
    __syncthreads();
    if (t < NEXP) g_count[t] = sc[t];
    if (t == 0) {
        int ni = 0;
        for (int e = 0; e < NEXP; e++) {
            int n = sc[e];
            for (int ch = 0; ch * NTILE < n && ni <= MAXITEMS - 4; ch++)
                for (int mt = 0; mt < 4; mt++)
                    g_items[ni++] = (e << 16) | (ch << 2) | mt;
        }
        g_nitems = ni;
    }
}

// ---------------- helpers ----------------
__device__ __forceinline__ uint32_t smem_u32(const void* p) {
    return (uint32_t)__cvta_generic_to_shared(p);
}
__device__ __forceinline__ uint4 cvt4_tf32(float4 v) {
    uint4 u;
    asm("cvt.rna.tf32.f32 %0, %1;" : "=r"(u.x) : "f"(v.x));
    asm("cvt.rna.tf32.f32 %0, %1;" : "=r"(u.y) : "f"(v.y));
    asm("cvt.rna.tf32.f32 %0, %1;" : "=r"(u.z) : "f"(v.z));
    asm("cvt.rna.tf32.f32 %0, %1;" : "=r"(u.w) : "f"(v.w));
    return u;
}
__device__ __forceinline__ void mma_tf32(float* d, const uint32_t* a,
                                         uint32_t b0, uint32_t b1) {
    asm volatile(
        "mma.sync.aligned.m16n8k8.row.col.f32.tf32.tf32.f32 "
        "{%0,%1,%2,%3}, {%4,%5,%6,%7}, {%8,%9}, {%0,%1,%2,%3};"
        : "+f"(d[0]), "+f"(d[1]), "+f"(d[2]), "+f"(d[3])
        : "r"(a[0]), "r"(a[1]), "r"(a[2]), "r"(a[3]), "r"(b0), "r"(b1));
}
__device__ __forceinline__ void ldm_x4(uint32_t* r, uint32_t addr) {
    asm volatile(
        "ldmatrix.sync.aligned.m8n8.x4.shared.b16 {%0,%1,%2,%3}, [%4];"
        : "=r"(r[0]), "=r"(r[1]), "=r"(r[2]), "=r"(r[3]) : "r"(addr));
}

// ---------------- grouped GEMM via mma.sync tf32 + ldmatrix ----------------
// Item (e, ch, mt): D[128 W-rows, 32 samples] = W_tile · x_chunk^T.
// 4 warps; warp w owns M-rows [w*32, w*32+32) (2 m16 tiles) x N=32 (4 n8 tiles).
__global__ __launch_bounds__(NT) void gemm_kernel(
    const float* __restrict__ x,
    const float* __restrict__ w,
    float* __restrict__ out)
{
    extern __shared__ uint32_t dsm[];
    uint32_t* Abuf[2] = { dsm,       dsm + A_F + B_F };
    uint32_t* Bbuf[2] = { dsm + A_F, dsm + 2 * A_F + B_F };
    __shared__ int sidx[NTILE];

    const int it = blockIdx.x;
    if (it >= g_nitems) return;

    const int t    = threadIdx.x;
    const int wrp  = t >> 5;
    const int lane = t & 31;
    const int ly   = lane >> 2;
    const int lx   = lane & 3;
    const int rb   = wrp * 32;

    const int pk = g_items[it];
    const int e  = pk >> 16;
    const int mt = pk & 3;
    const int ch = (pk >> 2) & 0x3fff;
    const int n  = g_count[e];
    const int nvalid = min(n - ch * NTILE, NTILE);
    const int* ls = g_list + e * BQ;

    if (t < NTILE) {
        int m = ch * NTILE + t;
        sidx[t] = ls[m < n ? m : n - 1];
    }
    __syncthreads();

    const float* wb = w + ((size_t)e * OUTD + (size_t)mt * MT) * IND;

    // ldmatrix lane-address selectors (same form for A and B):
    // tiles: lanes 0-7 -> T0, 8-15 -> T1, 16-23 -> T2, 24-31 -> T3
    // A x4 (per m16 tile i): T0 rows r..r+7 @k, T1 rows r+8..r+15 @k,
    //                        T2 rows r..r+7 @k+4, T3 @k+4  -> regs a0..a3
    // B x4 (per n16 pair p): T0 n p*16.. @k, T1 n p*16+8.. @k, T2/T3 @k+4
    //                        -> regs {b0(j0), b0(j1), b1(j0), b1(j1)}
    const int rsel = (lane & 7) + ((lane >> 3) & 1) * 8;
    const int csel = (lane >> 4) * 4;

    uint32_t aoff[2], boff[2];   // byte offsets within each buffer
    #pragma unroll
    for (int i = 0; i < 2; i++)
        aoff[i] = ((rb + i * 16 + rsel) * APITCH + csel) * 4;
    #pragma unroll
    for (int p = 0; p < 2; p++)
        boff[p] = ((p * 16 + rsel) * BPITCH + csel) * 4;

    uint32_t abase[2] = { smem_u32(Abuf[0]), smem_u32(Abuf[1]) };
    uint32_t bbase[2] = { smem_u32(Bbuf[0]), smem_u32(Bbuf[1]) };

    // fill mapping: A 1024 float4 (8/thread), B 256 float4 (2/thread)
    const int frow = t >> 3;
    const int fq4  = (t & 7) * 4;
    const float* xp[2];
    #pragma unroll
    for (int j = 0; j < 2; j++)
        xp[j] = x + (size_t)sidx[frow + 16 * j] * IND + fq4;

    float4 rw[8], rx[2];
    #pragma unroll
    for (int j = 0; j < 8; j++)
        rw[j] = *(const float4*)(wb + (size_t)(frow + 16 * j) * IND + fq4);
    #pragma unroll
    for (int j = 0; j < 2; j++)
        rx[j] = *(const float4*)(xp[j]);

    float acc[2][4][4];
    #pragma unroll
    for (int i = 0; i < 2; i++)
        #pragma unroll
        for (int j = 0; j < 4; j++)
            #pragma unroll
            for (int q = 0; q < 4; q++) acc[i][j][q] = 0.0f;

    for (int s = 0; s < NSTAGE; s++) {
        const int b = s & 1;
        uint32_t* Au = Abuf[b];
        uint32_t* Bu = Bbuf[b];

        // ---- STS stage s (cvt to tf32)
        #pragma unroll
        for (int j = 0; j < 8; j++)
            *(uint4*)&Au[(frow + 16 * j) * APITCH + fq4] = cvt4_tf32(rw[j]);
        #pragma unroll
        for (int j = 0; j < 2; j++)
            *(uint4*)&Bu[(frow + 16 * j) * BPITCH + fq4] = cvt4_tf32(rx[j]);
        __syncthreads();

        // ---- prefetch stage s+1 (overlaps mma below)
        if (s + 1 < NSTAGE) {
            int k0 = (s + 1) * BK;
            #pragma unroll
            for (int j = 0; j < 8; j++)
                rw[j] = *(const float4*)(wb + (size_t)(frow + 16 * j) * IND + k0 + fq4);
            #pragma unroll
            for (int j = 0; j < 2; j++)
                rx[j] = *(const float4*)(xp[j] + k0);
        }

        // ---- compute stage s: 4 ksteps x (2 ldm A + 2 ldm B + 8 mma)
        #pragma unroll
        for (int ks = 0; ks < 4; ks++) {
            const uint32_t kb = ks * 32;   // 8 floats
            uint32_t a[2][4], bf[2][4];
            ldm_x4(a[0], abase[b] + aoff[0] + kb);
            ldm_x4(a[1], abase[b] + aoff[1] + kb);
            ldm_x4(bf[0], bbase[b] + boff[0] + kb);
            ldm_x4(bf[1], bbase[b] + boff[1] + kb);
            #pragma unroll
            for (int p = 0; p < 2; p++) {
                mma_tf32(acc[0][2 * p + 0], a[0], bf[p][0], bf[p][2]);
                mma_tf32(acc[0][2 * p + 1], a[0], bf[p][1], bf[p][3]);
                mma_tf32(acc[1][2 * p + 0], a[1], bf[p][0], bf[p][2]);
                mma_tf32(acc[1][2 * p + 1], a[1], bf[p][1], bf[p][3]);
            }
        }
        __syncthreads();   // all warps done with buf b before refill at s+2
    }

    // ---- epilogue: frag (i,j): rows rb+i*16+ly(+8), cols j*8+lx*2(+1)
    float* ob = out + (size_t)mt * MT;
    #pragma unroll
    for (int i = 0; i < 2; i++) {
        #pragma unroll
        for (int j = 0; j < 4; j++) {
            int r0 = rb + i * 16 + ly;
            int r1 = r0 + 8;
            int c0 = j * 8 + lx * 2;
            int c1 = c0 + 1;
            if (c0 < nvalid) {
                size_t s0 = (size_t)sidx[c0] * OUTD;
                ob[s0 + r0] = acc[i][j][0];
                ob[s0 + r1] = acc[i][j][2];
            }
            if (c1 < nvalid) {
                size_t s1 = (size_t)sidx[c1] * OUTD;
                ob[s1 + r0] = acc[i][j][1];
                ob[s1 + r1] = acc[i][j][3];
            }
        }
    }
}

extern "C" void kernel_launch(void* const* d_in, const int* in_sizes, int n_in,
                              void* d_out, int out_size) {
    const float* x = nullptr;
    const int* ids = nullptr;
    const float* w = nullptr;
    for (int i = 0; i < n_in; i++) {
        if (in_sizes[i] == BQ * IND)                x   = (const float*)d_in[i];
        else if (in_sizes[i] == BQ)                 ids = (const int*)d_in[i];
        else if (in_sizes[i] == NEXP * OUTD * IND)  w   = (const float*)d_in[i];
    }
    float* out = (float*)d_out;

    cudaFuncSetAttribute(gemm_kernel,
                         cudaFuncAttributeMaxDynamicSharedMemorySize, SMEM_DYN);

    prep_kernel<<<1, 256>>>(ids);
    gemm_kernel<<<GRID_GEMM, NT, SMEM_DYN>>>(x, w, out);
}

// round 15
// speedup vs baseline: 1.1043x; 1.1043x over previous
#include <cuda_runtime.h>
#include <cstdint>

#define BQ     2048
#define IND    512
#define OUTD   512
#define NEXP   64

#define MT     128            // M: W rows per item
#define NTILE  64             // N: samples per item (W loaded exactly once)
#define BK     32             // k per stage
#define NSTAGE (IND / BK)     // 16
#define NBUF   3
#define NT     128            // 4 warps
#define GRID_GEMM 384
#define MAXITEMS 512

#define APITCH 36             // floats per A smem row (144B: ldmatrix conflict-free)
#define BPITCH 36
#define A_F    (MT * APITCH)        // 4608 floats
#define B_F    (NTILE * BPITCH)     // 2304 floats
#define STG_F  (A_F + B_F)          // 6912 floats per stage
#define SMEM_DYN (NBUF * STG_F * 4) // 82944 B

__device__ int g_count[NEXP];
__device__ int g_list[NEXP * BQ];
__device__ int g_items[MAXITEMS];
__device__ int g_nitems;

// ---------------- prep ----------------
__global__ void prep_kernel(const int* __restrict__ ids) {
    __shared__ int sc[NEXP];
    int t = threadIdx.x;
    if (t < NEXP) sc[t] = 0;
    __syncthreads();
    for (int i = t; i < BQ; i += blockDim.x) {
        int e = ids[i];
        if ((unsigned)e < NEXP) {
            int p = atomicAdd(&sc[e], 1);
            g_list[e * BQ + p] = i;
        }
    }
    __syncthreads();
    if (t < NEXP) g_count[t] = sc[t];
    if (t == 0) {
        int ni = 0;
        for (int e = 0; e < NEXP; e++) {
            int n = sc[e];
            for (int ch = 0; ch * NTILE < n && ni <= MAXITEMS - 4; ch++)
                for (int mt = 0; mt < 4; mt++)
                    g_items[ni++] = (e << 16) | (ch << 2) | mt;
        }
        g_nitems = ni;
    }
}

// ---------------- helpers ----------------
__device__ __forceinline__ uint32_t smem_u32(const void* p) {
    return (uint32_t)__cvta_generic_to_shared(p);
}
__device__ __forceinline__ void cp16(uint32_t dst, const void* src) {
    asm volatile("cp.async.cg.shared.global [%0], [%1], 16;" :: "r"(dst), "l"(src));
}
#define CP_COMMIT() asm volatile("cp.async.commit_group;" ::: "memory")
#define CP_WAIT1()  asm volatile("cp.async.wait_group 1;" ::: "memory")
#define CP_WAIT0()  asm volatile("cp.async.wait_group 0;" ::: "memory")

__device__ __forceinline__ void cvt4(uint32_t* r) {
    asm("cvt.rna.tf32.f32 %0, %0;" : "+r"(r[0]));
    asm("cvt.rna.tf32.f32 %0, %0;" : "+r"(r[1]));
    asm("cvt.rna.tf32.f32 %0, %0;" : "+r"(r[2]));
    asm("cvt.rna.tf32.f32 %0, %0;" : "+r"(r[3]));
}
__device__ __forceinline__ void mma_tf32(float* d, const uint32_t* a,
                                         uint32_t b0, uint32_t b1) {
    asm volatile(
        "mma.sync.aligned.m16n8k8.row.col.f32.tf32.tf32.f32 "
        "{%0,%1,%2,%3}, {%4,%5,%6,%7}, {%8,%9}, {%0,%1,%2,%3};"
        : "+f"(d[0]), "+f"(d[1]), "+f"(d[2]), "+f"(d[3])
        : "r"(a[0]), "r"(a[1]), "r"(a[2]), "r"(a[3]), "r"(b0), "r"(b1));
}
__device__ __forceinline__ void ldm_x4(uint32_t* r, uint32_t addr) {
    asm volatile(
        "ldmatrix.sync.aligned.m8n8.x4.shared.b16 {%0,%1,%2,%3}, [%4];"
        : "=r"(r[0]), "=r"(r[1]), "=r"(r[2]), "=r"(r[3]) : "r"(addr));
}

// ---------------- grouped GEMM: cp.async 3-stage + ldmatrix + tf32 mma ----------------
// Item (e, ch, mt): D[128 W-rows, 64 samples] = W_tile · x_chunk^T.
// 4 warps; warp w owns M-rows [w*32, w*32+32) (2 m16) x N=64 (8 n8 tiles).
__global__ __launch_bounds__(NT) void gemm_kernel(
    const float* __restrict__ x,
    const float* __restrict__ w,
    float* __restrict__ out)
{
    extern __shared__ float dsm[];
    __shared__ int sidx[NTILE];

    const int it = blockIdx.x;
    if (it >= g_nitems) return;

    const int t    = threadIdx.x;
    const int wrp  = t >> 5;
    const int lane = t & 31;
    const int ly   = lane >> 2;
    const int lx   = lane & 3;
    const int rb   = wrp * 32;

    const int pk = g_items[it];
    const int e  = pk >> 16;
    const int mt = pk & 3;
    const int ch = (pk >> 2) & 0x3fff;
    const int n  = g_count[e];
    const int nvalid = min(n - ch * NTILE, NTILE);
    const int* ls = g_list + e * BQ;

    if (t < NTILE) {
        int m = ch * NTILE + t;
        sidx[t] = ls[m < n ? m : n - 1];
    }
    __syncthreads();

    const float* wb = w + ((size_t)e * OUTD + (size_t)mt * MT) * IND;

    // fill mapping: frow = t>>3 (0..15), fq4 = (t&7)*4 floats (16B units)
    const int frow = t >> 3;
    const int fq4  = (t & 7) * 4;
    const float* xp[4];
    #pragma unroll
    for (int j = 0; j < 4; j++)
        xp[j] = x + (size_t)sidx[frow + 16 * j] * IND + fq4;

    // per-buffer smem byte bases for this thread's cp.async destinations
    const uint32_t sbase = smem_u32(dsm);
    uint32_t adst[NBUF], bdst[NBUF];
    #pragma unroll
    for (int bi = 0; bi < NBUF; bi++) {
        adst[bi] = sbase + (bi * STG_F + frow * APITCH + fq4) * 4;
        bdst[bi] = sbase + (bi * STG_F + A_F + frow * BPITCH + fq4) * 4;
    }

    // ldmatrix selectors (R14-verified): lanes 0-7:T0, 8-15:T1, 16-23:T2, 24-31:T3
    const int rsel = (lane & 7) + ((lane >> 3) & 1) * 8;
    const int csel = (lane >> 4) * 4;
    uint32_t aoff[2], boff[4];
    #pragma unroll
    for (int i = 0; i < 2; i++)
        aoff[i] = ((rb + i * 16 + rsel) * APITCH + csel) * 4;
    #pragma unroll
    for (int p = 0; p < 4; p++)
        boff[p] = ((A_F + (p * 16 + rsel) * BPITCH + csel)) * 4;

    // ---- issue stage helper (A: 8 rows, B: 4 rows per thread)
    auto issue = [&](int s) {
        const int bi = s % NBUF;
        const int k0 = s * BK;
        #pragma unroll
        for (int j = 0; j < 8; j++)
            cp16(adst[bi] + j * 16 * APITCH * 4,
                 wb + (size_t)(frow + 16 * j) * IND + k0 + fq4);
        #pragma unroll
        for (int j = 0; j < 4; j++)
            cp16(bdst[bi] + j * 16 * BPITCH * 4, xp[j] + k0);
        CP_COMMIT();
    };

    issue(0);
    issue(1);

    float acc[2][8][4];
    #pragma unroll
    for (int i = 0; i < 2; i++)
        #pragma unroll
        for (int j = 0; j < 8; j++)
            #pragma unroll
            for (int q = 0; q < 4; q++) acc[i][j][q] = 0.0f;

    for (int s = 0; s < NSTAGE; s++) {
        if (s < NSTAGE - 1) { CP_WAIT1(); } else { CP_WAIT0(); }
        __syncthreads();                 // stage s data visible; all warps past s-1
        if (s + 2 < NSTAGE) issue(s + 2);

        const uint32_t sbuf = sbase + (uint32_t)(s % NBUF) * STG_F * 4;
        #pragma unroll
        for (int ks = 0; ks < 4; ks++) {
            const uint32_t kb = ks * 32;   // 8 floats
            uint32_t a[2][4], bf[4][4];
            ldm_x4(a[0], sbuf + aoff[0] + kb);
            ldm_x4(a[1], sbuf + aoff[1] + kb);
            cvt4(a[0]); cvt4(a[1]);
            #pragma unroll
            for (int p = 0; p < 4; p++) {
                ldm_x4(bf[p], sbuf + boff[p] + kb);
                cvt4(bf[p]);
            }
            #pragma unroll
            for (int p = 0; p < 4; p++) {
                mma_tf32(acc[0][2 * p + 0], a[0], bf[p][0], bf[p][2]);
                mma_tf32(acc[0][2 * p + 1], a[0], bf[p][1], bf[p][3]);
                mma_tf32(acc[1][2 * p + 0], a[1], bf[p][0], bf[p][2]);
                mma_tf32(acc[1][2 * p + 1], a[1], bf[p][1], bf[p][3]);
            }
        }
        __syncthreads();                 // all warps done with buf s before reuse
    }

    // ---- epilogue: frag (i,j): rows rb+i*16+ly(+8), cols j*8+lx*2(+1)
    float* ob = out + (size_t)mt * MT;
    #pragma unroll
    for (int i = 0; i < 2; i++) {
        #pragma unroll
        for (int j = 0; j < 8; j++) {
            int r0 = rb + i * 16 + ly;
            int r1 = r0 + 8;
            int c0 = j * 8 + lx * 2;
            int c1 = c0 + 1;
            if (c0 < nvalid) {
                size_t s0 = (size_t)sidx[c0] * OUTD;
                ob[s0 + r0] = acc[i][j][0];
                ob[s0 + r1] = acc[i][j][2];
            }
            if (c1 < nvalid) {
                size_t s1 = (size_t)sidx[c1] * OUTD;
                ob[s1 + r0] = acc[i][j][1];
                ob[s1 + r1] = acc[i][j][3];
            }
        }
    }
}

extern "C" void kernel_launch(void* const* d_in, const int* in_sizes, int n_in,
                              void* d_out, int out_size) {
    const float* x = nullptr;
    const int* ids = nullptr;
    const float* w = nullptr;
    for (int i = 0; i < n_in; i++) {
        if (in_sizes[i] == BQ * IND)                x   = (const float*)d_in[i];
        else if (in_sizes[i] == BQ)                 ids = (const int*)d_in[i];
        else if (in_sizes[i] == NEXP * OUTD * IND)  w   = (const float*)d_in[i];
    }
    float* out = (float*)d_out;

    cudaFuncSetAttribute(gemm_kernel,
                         cudaFuncAttributeMaxDynamicSharedMemorySize, SMEM_DYN);

    prep_kernel<<<1, 256>>>(ids);
    gemm_kernel<<<GRID_GEMM, NT, SMEM_DYN>>>(x, w, out);
}

// round 16
// speedup vs baseline: 1.1120x; 1.0069x over previous
#include <cuda_runtime.h>
#include <cstdint>

#define BQ     2048
#define IND    512
#define OUTD   512
#define NEXP   64

#define MT     128            // M: W rows per item
#define NTILE  64             // N: samples per item (W loaded exactly once)
#define BK     32             // k per stage
#define NSTAGE (IND / BK)     // 16
#define NBUF   3
#define NT     128            // 4 warps
#define GRID_GEMM 384
#define MAXITEMS 512

#define APITCH 36             // floats per A smem row (144B: ldmatrix conflict-free)
#define BPITCH 36
#define A_F    (MT * APITCH)        // 4608 floats
#define B_F    (NTILE * BPITCH)     // 2304 floats
#define STG_F  (A_F + B_F)          // 6912 floats per stage
#define SMEM_DYN (NBUF * STG_F * 4) // 82944 B

__device__ int g_count[NEXP];
__device__ int g_list[NEXP * BQ];
__device__ int g_items[MAXITEMS];
__device__ int g_nitems;

// ---------------- prep ----------------
__global__ void prep_kernel(const int* __restrict__ ids) {
    __shared__ int sc[NEXP];
    int t = threadIdx.x;
    if (t < NEXP) sc[t] = 0;
    __syncthreads();
    for (int i = t; i < BQ; i += blockDim.x) {
        int e = ids[i];
        if ((unsigned)e < NEXP) {
            int p = atomicAdd(&sc[e], 1);
            g_list[e * BQ + p] = i;
        }
    }
    __syncthreads();
    if (t < NEXP) g_count[t] = sc[t];
    if (t == 0) {
        int ni = 0;
        for (int e = 0; e < NEXP; e++) {
            int n = sc[e];
            for (int ch = 0; ch * NTILE < n && ni <= MAXITEMS - 4; ch++)
                for (int mt = 0; mt < 4; mt++)
                    g_items[ni++] = (e << 16) | (ch << 2) | mt;
        }
        g_nitems = ni;
    }
}

// ---------------- helpers ----------------
__device__ __forceinline__ uint32_t smem_u32(const void* p) {
    return (uint32_t)__cvta_generic_to_shared(p);
}
__device__ __forceinline__ void cp16(uint32_t dst, const void* src) {
    asm volatile("cp.async.cg.shared.global [%0], [%1], 16;" :: "r"(dst), "l"(src));
}
#define CP_COMMIT() asm volatile("cp.async.commit_group;" ::: "memory")
#define CP_WAIT1()  asm volatile("cp.async.wait_group 1;" ::: "memory")
#define CP_WAIT0()  asm volatile("cp.async.wait_group 0;" ::: "memory")

__device__ __forceinline__ void cvt4(uint32_t* r) {
    asm("cvt.rna.tf32.f32 %0, %0;" : "+r"(r[0]));
    asm("cvt.rna.tf32.f32 %0, %0;" : "+r"(r[1]));
    asm("cvt.rna.tf32.f32 %0, %0;" : "+r"(r[2]));
    asm("cvt.rna.tf32.f32 %0, %0;" : "+r"(r[3]));
}
__device__ __forceinline__ void mma_tf32(float* d, const uint32_t* a,
                                         uint32_t b0, uint32_t b1) {
    asm volatile(
        "mma.sync.aligned.m16n8k8.row.col.f32.tf32.tf32.f32 "
        "{%0,%1,%2,%3}, {%4,%5,%6,%7}, {%8,%9}, {%0,%1,%2,%3};"
        : "+f"(d[0]), "+f"(d[1]), "+f"(d[2]), "+f"(d[3])
        : "r"(a[0]), "r"(a[1]), "r"(a[2]), "r"(a[3]), "r"(b0), "r"(b1));
}
__device__ __forceinline__ void ldm_x4(uint32_t* r, uint32_t addr) {
    asm volatile(
        "ldmatrix.sync.aligned.m8n8.x4.shared.b16 {%0,%1,%2,%3}, [%4];"
        : "=r"(r[0]), "=r"(r[1]), "=r"(r[2]), "=r"(r[3]) : "r"(addr));
}

// ---------------- grouped GEMM: cp.async 3-stage + ldmatrix + tf32 mma ----------------
// Item (e, ch, mt): D[128 W-rows, 64 samples] = W_tile · x_chunk^T.
// 4 warps; warp w owns M-rows [w*32, w*32+32) (2 m16) x N=64 (8 n8 tiles).
// Fragments register-double-buffered across k-steps to hide LDS latency.
__global__ __launch_bounds__(NT) void gemm_kernel(
    const float* __restrict__ x,
    const float* __restrict__ w,
    float* __restrict__ out)
{
    extern __shared__ float dsm[];
    __shared__ int sidx[NTILE];

    const int it = blockIdx.x;
    if (it >= g_nitems) return;

    const int t    = threadIdx.x;
    const int wrp  = t >> 5;
    const int lane = t & 31;
    const int ly   = lane >> 2;
    const int lx   = lane & 3;
    const int rb   = wrp * 32;

    const int pk = g_items[it];
    const int e  = pk >> 16;
    const int mt = pk & 3;
    const int ch = (pk >> 2) & 0x3fff;
    const int n  = g_count[e];
    const int nvalid = min(n - ch * NTILE, NTILE);
    const int* ls = g_list + e * BQ;

    if (t < NTILE) {
        int m = ch * NTILE + t;
        sidx[t] = ls[m < n ? m : n - 1];
    }
    __syncthreads();

    const float* wb = w + ((size_t)e * OUTD + (size_t)mt * MT) * IND;

    // fill mapping: frow = t>>3 (0..15), fq4 = (t&7)*4 floats (16B units)
    const int frow = t >> 3;
    const int fq4  = (t & 7) * 4;
    const float* xp[4];
    #pragma unroll
    for (int j = 0; j < 4; j++)
        xp[j] = x + (size_t)sidx[frow + 16 * j] * IND + fq4;

    const uint32_t sbase = smem_u32(dsm);
    uint32_t adst[NBUF], bdst[NBUF];
    #pragma unroll
    for (int bi = 0; bi < NBUF; bi++) {
        adst[bi] = sbase + (bi * STG_F + frow * APITCH + fq4) * 4;
        bdst[bi] = sbase + (bi * STG_F + A_F + frow * BPITCH + fq4) * 4;
    }

    // ldmatrix selectors (verified): lanes 0-7:T0, 8-15:T1, 16-23:T2, 24-31:T3
    const int rsel = (lane & 7) + ((lane >> 3) & 1) * 8;
    const int csel = (lane >> 4) * 4;
    uint32_t aoff[2], boff[4];
    #pragma unroll
    for (int i = 0; i < 2; i++)
        aoff[i] = ((rb + i * 16 + rsel) * APITCH + csel) * 4;
    #pragma unroll
    for (int p = 0; p < 4; p++)
        boff[p] = ((A_F + (p * 16 + rsel) * BPITCH + csel)) * 4;

    auto issue = [&](int s) {
        const int bi = s % NBUF;
        const int k0 = s * BK;
        #pragma unroll
        for (int j = 0; j < 8; j++)
            cp16(adst[bi] + j * 16 * APITCH * 4,
                 wb + (size_t)(frow + 16 * j) * IND + k0 + fq4);
        #pragma unroll
        for (int j = 0; j < 4; j++)
            cp16(bdst[bi] + j * 16 * BPITCH * 4, xp[j] + k0);
        CP_COMMIT();
    };

    issue(0);
    issue(1);

    float acc[2][8][4];
    #pragma unroll
    for (int i = 0; i < 2; i++)
        #pragma unroll
        for (int j = 0; j < 8; j++)
            #pragma unroll
            for (int q = 0; q < 4; q++) acc[i][j][q] = 0.0f;

    for (int s = 0; s < NSTAGE; s++) {
        if (s < NSTAGE - 1) { CP_WAIT1(); } else { CP_WAIT0(); }
        __syncthreads();        // single barrier/stage; NBUF=3 makes tail sync redundant
        if (s + 2 < NSTAGE) issue(s + 2);

        const uint32_t sbuf = sbase + (uint32_t)(s % NBUF) * STG_F * 4;

        // fragment double buffer: pb = parity of ks
        uint32_t afr[2][2][4], bfr[2][4][4];
        ldm_x4(afr[0][0], sbuf + aoff[0]);
        ldm_x4(afr[0][1], sbuf + aoff[1]);
        #pragma unroll
        for (int p = 0; p < 4; p++) ldm_x4(bfr[0][p], sbuf + boff[p]);

        #pragma unroll
        for (int ks = 0; ks < 4; ks++) {
            const int cur = ks & 1;
            const int nxt = cur ^ 1;
            if (ks < 3) {
                const uint32_t kb = (ks + 1) * 32;   // 8 floats
                ldm_x4(afr[nxt][0], sbuf + aoff[0] + kb);
                ldm_x4(afr[nxt][1], sbuf + aoff[1] + kb);
                #pragma unroll
                for (int p = 0; p < 4; p++)
                    ldm_x4(bfr[nxt][p], sbuf + boff[p] + kb);
            }
            cvt4(afr[cur][0]); cvt4(afr[cur][1]);
            #pragma unroll
            for (int p = 0; p < 4; p++) cvt4(bfr[cur][p]);
            #pragma unroll
            for (int p = 0; p < 4; p++) {
                mma_tf32(acc[0][2 * p + 0], afr[cur][0], bfr[cur][p][0], bfr[cur][p][2]);
                mma_tf32(acc[0][2 * p + 1], afr[cur][0], bfr[cur][p][1], bfr[cur][p][3]);
                mma_tf32(acc[1][2 * p + 0], afr[cur][1], bfr[cur][p][0], bfr[cur][p][2]);
                mma_tf32(acc[1][2 * p + 1], afr[cur][1], bfr[cur][p][1], bfr[cur][p][3]);
            }
        }
    }

    // ---- epilogue: frag (i,j): rows rb+i*16+ly(+8), cols j*8+lx*2(+1)
    float* ob = out + (size_t)mt * MT;
    #pragma unroll
    for (int i = 0; i < 2; i++) {
        #pragma unroll
        for (int j = 0; j < 8; j++) {
            int r0 = rb + i * 16 + ly;
            int r1 = r0 + 8;
            int c0 = j * 8 + lx * 2;
            int c1 = c0 + 1;
            if (c0 < nvalid) {
                size_t s0 = (size_t)sidx[c0] * OUTD;
                ob[s0 + r0] = acc[i][j][0];
                ob[s0 + r1] = acc[i][j][2];
            }
            if (c1 < nvalid) {
                size_t s1 = (size_t)sidx[c1] * OUTD;
                ob[s1 + r0] = acc[i][j][1];
                ob[s1 + r1] = acc[i][j][3];
            }
        }
    }
}

extern "C" void kernel_launch(void* const* d_in, const int* in_sizes, int n_in,
                              void* d_out, int out_size) {
    const float* x = nullptr;
    const int* ids = nullptr;
    const float* w = nullptr;
    for (int i = 0; i < n_in; i++) {
        if (in_sizes[i] == BQ * IND)                x   = (const float*)d_in[i];
        else if (in_sizes[i] == BQ)                 ids = (const int*)d_in[i];
        else if (in_sizes[i] == NEXP * OUTD * IND)  w   = (const float*)d_in[i];
    }
    float* out = (float*)d_out;

    cudaFuncSetAttribute(gemm_kernel,
                         cudaFuncAttributeMaxDynamicSharedMemorySize, SMEM_DYN);

    prep_kernel<<<1, 256>>>(ids);
    gemm_kernel<<<GRID_GEMM, NT, SMEM_DYN>>>(x, w, out);
}

// round 17
// speedup vs baseline: 1.3112x; 1.1791x over previous
#include <cuda_runtime.h>
#include <cstdint>

#define BQ     2048
#define IND    512
#define OUTD   512
#define NEXP   64

#define MT     128            // M: W rows per item
#define NTILE  64             // N: samples per item (W loaded exactly once)
#define BK     32             // k per stage
#define NSTAGE (IND / BK)     // 16
#define NBUF   3
#define NT     256            // 8 warps, warp tile m16 x n64
#define GRID_GEMM 384
#define MAXITEMS 512

#define APITCH 36             // floats per A smem row (144B: ldmatrix conflict-free)
#define BPITCH 36
#define A_F    (MT * APITCH)        // 4608 floats
#define B_F    (NTILE * BPITCH)     // 2304 floats
#define STG_F  (A_F + B_F)          // 6912 floats per stage
#define SMEM_DYN (NBUF * STG_F * 4) // 82944 B

__device__ int g_count[NEXP];
__device__ int g_list[NEXP * BQ];
__device__ int g_items[MAXITEMS];
__device__ int g_nitems;

// ---------------- prep (fully parallel item emission) ----------------
__global__ void prep_kernel(const int* __restrict__ ids) {
    __shared__ int sc[NEXP];
    __shared__ int tot;
    int t = threadIdx.x;
    if (t < NEXP) sc[t] = 0;
    if (t == 0) tot = 0;
    __syncthreads();
    for (int i = t; i < BQ; i += blockDim.x) {
        int e = ids[i];
        if ((unsigned)e < NEXP) {
            int p = atomicAdd(&sc[e], 1);
            g_list[e * BQ + p] = i;
        }
    }
    __syncthreads();
    if (t < NEXP) {
        int n = sc[t];
        g_count[t] = n;
        int nch = (n + NTILE - 1) / NTILE;
        if (nch > 0) {
            int base = atomicAdd(&tot, nch * 4);
            for (int c = 0; c < nch; c++)
                for (int mt = 0; mt < 4; mt++)
                    if (base < MAXITEMS)
                        g_items[base++] = (t << 16) | (c << 2) | mt;
        }
    }
    __syncthreads();
    if (t == 0) g_nitems = min(tot, MAXITEMS);
}

// ---------------- helpers ----------------
__device__ __forceinline__ uint32_t smem_u32(const void* p) {
    return (uint32_t)__cvta_generic_to_shared(p);
}
__device__ __forceinline__ void cp16(uint32_t dst, const void* src) {
    asm volatile("cp.async.cg.shared.global [%0], [%1], 16;" :: "r"(dst), "l"(src));
}
#define CP_COMMIT() asm volatile("cp.async.commit_group;" ::: "memory")
#define CP_WAIT1()  asm volatile("cp.async.wait_group 1;" ::: "memory")
#define CP_WAIT0()  asm volatile("cp.async.wait_group 0;" ::: "memory")

__device__ __forceinline__ void cvt4(uint32_t* r) {
    asm("cvt.rna.tf32.f32 %0, %0;" : "+r"(r[0]));
    asm("cvt.rna.tf32.f32 %0, %0;" : "+r"(r[1]));
    asm("cvt.rna.tf32.f32 %0, %0;" : "+r"(r[2]));
    asm("cvt.rna.tf32.f32 %0, %0;" : "+r"(r[3]));
}
__device__ __forceinline__ void mma_tf32(float* d, const uint32_t* a,
                                         uint32_t b0, uint32_t b1) {
    asm volatile(
        "mma.sync.aligned.m16n8k8.row.col.f32.tf32.tf32.f32 "
        "{%0,%1,%2,%3}, {%4,%5,%6,%7}, {%8,%9}, {%0,%1,%2,%3};"
        : "+f"(d[0]), "+f"(d[1]), "+f"(d[2]), "+f"(d[3])
        : "r"(a[0]), "r"(a[1]), "r"(a[2]), "r"(a[3]), "r"(b0), "r"(b1));
}
__device__ __forceinline__ void ldm_x4(uint32_t* r, uint32_t addr) {
    asm volatile(
        "ldmatrix.sync.aligned.m8n8.x4.shared.b16 {%0,%1,%2,%3}, [%4];"
        : "=r"(r[0]), "=r"(r[1]), "=r"(r[2]), "=r"(r[3]) : "r"(addr));
}

// ---------------- grouped GEMM: cp.async 3-stage + ldmatrix + tf32 mma ----------------
// Item (e, ch, mt): D[128 W-rows, 64 samples] = W_tile · x_chunk^T.
// 8 warps; warp w owns M-rows [w*16, w*16+16) (one m16 tile) x N=64 (8 n8 tiles).
__global__ __launch_bounds__(NT, 2) void gemm_kernel(
    const float* __restrict__ x,
    const float* __restrict__ w,
    float* __restrict__ out)
{
    extern __shared__ float dsm[];
    __shared__ int sidx[NTILE];

    const int it = blockIdx.x;
    if (it >= g_nitems) return;

    const int t    = threadIdx.x;
    const int wrp  = t >> 5;
    const int lane = t & 31;
    const int ly   = lane >> 2;
    const int lx   = lane & 3;
    const int rb   = wrp * 16;

    const int pk = g_items[it];
    const int e  = pk >> 16;
    const int mt = pk & 3;
    const int ch = (pk >> 2) & 0x3fff;
    const int n  = g_count[e];
    const int nvalid = min(n - ch * NTILE, NTILE);
    const int* ls = g_list + e * BQ;

    if (t < NTILE) {
        int m = ch * NTILE + t;
        sidx[t] = ls[m < n ? m : n - 1];
    }
    __syncthreads();

    const float* wb = w + ((size_t)e * OUTD + (size_t)mt * MT) * IND;

    // fill mapping: frow = t>>3 (0..31), fq4 = (t&7)*4 floats (16B units)
    const int frow = t >> 3;
    const int fq4  = (t & 7) * 4;
    const float* xp[2];
    #pragma unroll
    for (int j = 0; j < 2; j++)
        xp[j] = x + (size_t)sidx[frow + 32 * j] * IND + fq4;

    const uint32_t sbase = smem_u32(dsm);
    uint32_t adst[NBUF], bdst[NBUF];
    #pragma unroll
    for (int bi = 0; bi < NBUF; bi++) {
        adst[bi] = sbase + (bi * STG_F + frow * APITCH + fq4) * 4;
        bdst[bi] = sbase + (bi * STG_F + A_F + frow * BPITCH + fq4) * 4;
    }

    // ldmatrix selectors (verified): lanes 0-7:T0, 8-15:T1, 16-23:T2, 24-31:T3
    const int rsel = (lane & 7) + ((lane >> 3) & 1) * 8;
    const int csel = (lane >> 4) * 4;
    const uint32_t aoff = ((rb + rsel) * APITCH + csel) * 4;
    uint32_t boff[4];
    #pragma unroll
    for (int p = 0; p < 4; p++)
        boff[p] = ((A_F + (p * 16 + rsel) * BPITCH + csel)) * 4;

    auto issue = [&](int s) {
        const int bi = s % NBUF;
        const int k0 = s * BK;
        #pragma unroll
        for (int j = 0; j < 4; j++)          // A: 128 rows, 4 per thread
            cp16(adst[bi] + j * 32 * APITCH * 4,
                 wb + (size_t)(frow + 32 * j) * IND + k0 + fq4);
        #pragma unroll
        for (int j = 0; j < 2; j++)          // B: 64 rows, 2 per thread
            cp16(bdst[bi] + j * 32 * BPITCH * 4, xp[j] + k0);
        CP_COMMIT();
    };

    issue(0);
    issue(1);

    float acc[8][4];
    #pragma unroll
    for (int j = 0; j < 8; j++)
        #pragma unroll
        for (int q = 0; q < 4; q++) acc[j][q] = 0.0f;

    for (int s = 0; s < NSTAGE; s++) {
        if (s < NSTAGE - 1) { CP_WAIT1(); } else { CP_WAIT0(); }
        __syncthreads();        // single barrier/stage; NBUF=3 covers WAR on issue
        if (s + 2 < NSTAGE) issue(s + 2);

        const uint32_t sbuf = sbase + (uint32_t)(s % NBUF) * STG_F * 4;

        // fragment double buffer across k-steps
        uint32_t afr[2][4], bfr[2][4][4];
        ldm_x4(afr[0], sbuf + aoff);
        #pragma unroll
        for (int p = 0; p < 4; p++) ldm_x4(bfr[0][p], sbuf + boff[p]);

        #pragma unroll
        for (int ks = 0; ks < 4; ks++) {
            const int cur = ks & 1;
            const int nxt = cur ^ 1;
            if (ks < 3) {
                const uint32_t kb = (ks + 1) * 32;   // 8 floats
                ldm_x4(afr[nxt], sbuf + aoff + kb);
                #pragma unroll
                for (int p = 0; p < 4; p++)
                    ldm_x4(bfr[nxt][p], sbuf + boff[p] + kb);
            }
            cvt4(afr[cur]);
            #pragma unroll
            for (int p = 0; p < 4; p++) cvt4(bfr[cur][p]);
            #pragma unroll
            for (int p = 0; p < 4; p++) {
                mma_tf32(acc[2 * p + 0], afr[cur], bfr[cur][p][0], bfr[cur][p][2]);
                mma_tf32(acc[2 * p + 1], afr[cur], bfr[cur][p][1], bfr[cur][p][3]);
            }
        }
    }

    // ---- epilogue: frag j: rows rb+ly (acc[j][0,1]) and rb+8+ly (acc[j][2,3]),
    //      cols j*8+lx*2 and +1
    float* ob = out + (size_t)mt * MT;
    #pragma unroll
    for (int j = 0; j < 8; j++) {
        int r0 = rb + ly;
        int r1 = r0 + 8;
        int c0 = j * 8 + lx * 2;
        int c1 = c0 + 1;
        if (c0 < nvalid) {
            size_t s0 = (size_t)sidx[c0] * OUTD;
            ob[s0 + r0] = acc[j][0];
            ob[s0 + r1] = acc[j][2];
        }
        if (c1 < nvalid) {
            size_t s1 = (size_t)sidx[c1] * OUTD;
            ob[s1 + r0] = acc[j][1];
            ob[s1 + r1] = acc[j][3];
        }
    }
}

extern "C" void kernel_launch(void* const* d_in, const int* in_sizes, int n_in,
                              void* d_out, int out_size) {
    const float* x = nullptr;
    const int* ids = nullptr;
    const float* w = nullptr;
    for (int i = 0; i < n_in; i++) {
        if (in_sizes[i] == BQ * IND)                x   = (const float*)d_in[i];
        else if (in_sizes[i] == BQ)                 ids = (const int*)d_in[i];
        else if (in_sizes[i] == NEXP * OUTD * IND)  w   = (const float*)d_in[i];
    }
    float* out = (float*)d_out;

    cudaFuncSetAttribute(gemm_kernel,
                         cudaFuncAttributeMaxDynamicSharedMemorySize, SMEM_DYN);

    prep_kernel<<<1, 256>>>(ids);
    gemm_kernel<<<GRID_GEMM, NT, SMEM_DYN>>>(x, w, out);
}